// round 2
// baseline (speedup 1.0000x reference)
#include <cuda_runtime.h>
#include <math.h>

#define BB   4
#define NN   512
#define DD   128
#define OUTD 128
#define M_TOTAL (BB * NN)   // 2048

// Scratch (device globals: no allocation allowed in kernel_launch)
__device__ float g_Pb[M_TOTAL * OUTD];  // P + bias
__device__ float g_Q [M_TOTAL * OUTD];  // x @ W2

static __device__ __forceinline__ float4 f4max(float4 a, float4 b) {
    float4 r;
    r.x = fmaxf(a.x, b.x); r.y = fmaxf(a.y, b.y);
    r.z = fmaxf(a.z, b.z); r.w = fmaxf(a.w, b.w);
    return r;
}

// ---------------------------------------------------------------------------
// Kernel 1: fused dual GEMM.
//   P[m,o] = sum_k x[m,k] * (W[k,o] - W[k+128,o]) ;  Pb = P + bias
//   Q[m,o] = sum_k x[m,k] *  W[k+128,o]
// Block: 256 threads = 8 warps; each warp computes 2 rows, each lane owns a
// float4 column group (o = lane*4 .. lane*4+3). 16 rows/block -> 128 blocks.
// ---------------------------------------------------------------------------
__global__ __launch_bounds__(256, 2)
void ec_gemm_kernel(const float* __restrict__ x,
                    const float* __restrict__ W,
                    const float* __restrict__ bias) {
    __shared__ float xs[16][DD];

    const int tid     = threadIdx.x;
    const int rowBase = blockIdx.x * 16;

    // cooperative load of x tile: 16*128 = 2048 floats = 512 float4
    {
        const float4* x4  = (const float4*)(x + (size_t)rowBase * DD);
        float4*       xs4 = (float4*)&xs[0][0];
        xs4[tid]       = x4[tid];
        xs4[tid + 256] = x4[tid + 256];
    }
    __syncthreads();

    const int w    = tid >> 5;
    const int lane = tid & 31;
    const int r0   = w * 2;          // local row pair

    float4 aP0 = make_float4(0.f, 0.f, 0.f, 0.f);
    float4 aP1 = aP0, aQ0 = aP0, aQ1 = aP0;

    const float4* __restrict__ W4 = (const float4*)W;  // row k: 32 float4

    #pragma unroll 8
    for (int k = 0; k < DD; ++k) {
        float4 w1 = W4[k * 32 + lane];
        float4 w2 = W4[(k + DD) * 32 + lane];
        float4 wd;
        wd.x = w1.x - w2.x; wd.y = w1.y - w2.y;
        wd.z = w1.z - w2.z; wd.w = w1.w - w2.w;

        float xa = xs[r0][k];
        float xb = xs[r0 + 1][k];

        aP0.x = fmaf(xa, wd.x, aP0.x); aP0.y = fmaf(xa, wd.y, aP0.y);
        aP0.z = fmaf(xa, wd.z, aP0.z); aP0.w = fmaf(xa, wd.w, aP0.w);
        aQ0.x = fmaf(xa, w2.x, aQ0.x); aQ0.y = fmaf(xa, w2.y, aQ0.y);
        aQ0.z = fmaf(xa, w2.z, aQ0.z); aQ0.w = fmaf(xa, w2.w, aQ0.w);

        aP1.x = fmaf(xb, wd.x, aP1.x); aP1.y = fmaf(xb, wd.y, aP1.y);
        aP1.z = fmaf(xb, wd.z, aP1.z); aP1.w = fmaf(xb, wd.w, aP1.w);
        aQ1.x = fmaf(xb, w2.x, aQ1.x); aQ1.y = fmaf(xb, w2.y, aQ1.y);
        aQ1.z = fmaf(xb, w2.z, aQ1.z); aQ1.w = fmaf(xb, w2.w, aQ1.w);
    }

    const float4 b4 = ((const float4*)bias)[lane];
    const int m0 = rowBase + r0;

    float4* P4 = (float4*)g_Pb;
    float4* Q4 = (float4*)g_Q;

    float4 o0; o0.x = aP0.x + b4.x; o0.y = aP0.y + b4.y;
               o0.z = aP0.z + b4.z; o0.w = aP0.w + b4.w;
    float4 o1; o1.x = aP1.x + b4.x; o1.y = aP1.y + b4.y;
               o1.z = aP1.z + b4.z; o1.w = aP1.w + b4.w;

    P4[(size_t)m0 * 32 + lane]       = o0;
    P4[(size_t)(m0 + 1) * 32 + lane] = o1;
    Q4[(size_t)m0 * 32 + lane]       = aQ0;
    Q4[(size_t)(m0 + 1) * 32 + lane] = aQ1;
}

// ---------------------------------------------------------------------------
// Kernel 2: masked neighbor max + epilogue.
//   out[b,i,o] = max(0, Pb[b,i,o] + max_{j: adj[b,i,j]>0} Q[b,j,o])
// One block per (b,i): 128 threads = 4 warps. Warp w scans j in [w*128,(w+1)*128)
// using ballot over the adj row (in smem) and iterates only set bits.
// Lane owns float4 group o = lane*4. Cross-warp reduce via smem.
// ---------------------------------------------------------------------------
__global__ __launch_bounds__(128)
void ec_maxred_kernel(const float* __restrict__ adj,
                      float* __restrict__ out) {
    __shared__ float  adj_s[NN];
    __shared__ float4 part[4 * 32];

    const int bi   = blockIdx.x;        // b*NN + i
    const int b    = bi >> 9;
    const int tid  = threadIdx.x;
    const int w    = tid >> 5;
    const int lane = tid & 31;

    // load adj row (512 floats) via float4
    ((float4*)adj_s)[tid] = ((const float4*)(adj + (size_t)bi * NN))[tid];
    __syncthreads();

    const float4* __restrict__ Q4 = ((const float4*)g_Q) + (size_t)b * NN * 32;

    const float NEG = -INFINITY;
    float4 acc = make_float4(NEG, NEG, NEG, NEG);

    const int j0 = w * 128;
    #pragma unroll
    for (int g = 0; g < 4; ++g) {
        const int jg = j0 + g * 32;
        unsigned mask = __ballot_sync(0xffffffffu, adj_s[jg + lane] > 0.0f);
        while (mask) {
            const int jj = __ffs(mask) - 1;
            mask &= mask - 1;
            const float4 q = Q4[(size_t)(jg + jj) * 32 + lane];
            acc = f4max(acc, q);
        }
    }

    part[w * 32 + lane] = acc;
    __syncthreads();

    if (tid < 32) {
        float4 m = part[tid];
        m = f4max(m, part[32 + tid]);
        m = f4max(m, part[64 + tid]);
        m = f4max(m, part[96 + tid]);

        const float4 p = ((const float4*)g_Pb)[(size_t)bi * 32 + tid];
        float4 r;
        r.x = fmaxf(0.f, p.x + m.x);
        r.y = fmaxf(0.f, p.y + m.y);
        r.z = fmaxf(0.f, p.z + m.z);
        r.w = fmaxf(0.f, p.w + m.w);
        ((float4*)out)[(size_t)bi * 32 + tid] = r;
    }
}

// ---------------------------------------------------------------------------
extern "C" void kernel_launch(void* const* d_in, const int* in_sizes, int n_in,
                              void* d_out, int out_size) {
    const float* x    = (const float*)d_in[0];   // (4,512,128)
    const float* adj  = (const float*)d_in[1];   // (4,512,512)
    const float* W    = (const float*)d_in[2];   // (256,128)
    const float* bias = (const float*)d_in[3];   // (128,)
    float*       out  = (float*)d_out;           // (4,512,128)

    ec_gemm_kernel<<<M_TOTAL / 16, 256>>>(x, W, bias);
    ec_maxred_kernel<<<M_TOTAL, 128>>>(adj, out);
}